// round 10
// baseline (speedup 1.0000x reference)
#include <cuda_runtime.h>
#include <cstddef>
#include <cstdint>

// DCTFeatureModel — collapsed linear model:
// feat[b,s,o] = sum_{t,ij} xc[b,s,t,ij] * Veff[s,o,t,ij] + bias[s,o]
//   xc[b,s,t,ij]    = sum_c x[b, s*256 + c*32 + t, ij]
//   Veff[s,o,t,i,j] = (1/8) sum_{f,p,q} Ct[f,t] Cs[p,i] Cs[q,j] W[s,o,f,p,q]
// out[b, s*64+o] = leaky_relu(feat)
//
// kernel 1: prep v3 — CTA=(s, t-pair, o-quarter), coalesced W stream,
//           per-stage thread remap, coalesced veff stores.
// kernel 2: main — R4-exact GEMM core + fused last-CTA epilogue.

#define NSW 2
#define NF 64
#define KSPLIT 16
#define MTILES 16

__device__ __align__(16) float g_veff[NSW * 32 * 64 * 64];        // [s][t][ij][o], 1 MB
__device__ __align__(16) float g_part[KSPLIT * 1024 * NSW * NF];  // 8 MB
__device__ int g_grp[32];   // per-(s,mt) arrival counters (winner self-resets)
__device__ int g_done;      // reducer counter (last self-resets)

typedef unsigned long long u64;

__device__ __forceinline__ u64 pk2(float a, float b) {
    u64 r; asm("mov.b64 %0,{%1,%2};" : "=l"(r) : "f"(a), "f"(b)); return r;
}
__device__ __forceinline__ float2 up2(u64 a) {
    float2 v; asm("mov.b64 {%0,%1},%2;" : "=f"(v.x), "=f"(v.y) : "l"(a)); return v;
}
__device__ __forceinline__ void fma2(u64& d, u64 a, u64 b) {
    asm("fma.rn.f32x2 %0,%1,%2,%0;" : "+l"(d) : "l"(a), "l"(b));
}
__device__ __forceinline__ u64 add2(u64 a, u64 b) {
    u64 r; asm("add.rn.f32x2 %0,%1,%2;" : "=l"(r) : "l"(a), "l"(b)); return r;
}

// ---------------------------------------------------------------------------
// prep v3: CTA = (s, tp, oq): t in {2tp, 2tp+1}, o in [oq*16, oq*16+16).
// Grid = 2*16*4 = 128. Reads W[s][oq*16..+16][*][*] coalesced (128 KB/CTA),
// writes g_veff[s][t][ij][o-sixteenth] coalesced along o.
// ---------------------------------------------------------------------------
__global__ void __launch_bounds__(256) prep_kernel(const float* __restrict__ W) {
    __shared__ __align__(16) float Y1[2][16][68];   // [t][o_local][pq], pad 68
    __shared__ __align__(16) float Y2[2][16][68];   // [t][o_local][i*8+q]
    __shared__ __align__(16) float Ct2[2][32];      // [th][f]
    __shared__ __align__(16) float Cs[64];          // [i][p]
    __shared__ __align__(16) float Cst[64];         // [q][j]

    const int tid = threadIdx.x;
    const int bx = blockIdx.x;          // s*64 + tp*4 + oq
    const int oq = bx & 3;
    const int tp = (bx >> 2) & 15;
    const int s = bx >> 6;

    // tables
    if (tid < 64) {
        int th = tid >> 5, f = tid & 31;
        int t = 2 * tp + th;
        Ct2[th][f] = 2.0f * cospif((float)((2 * t + 1) * f) / 64.0f);
    } else if (tid < 128) {
        int e = tid - 64, i = e >> 3, p = e & 7;
        Cs[e] = 2.0f * cospif((float)((2 * i + 1) * p) / 16.0f);
    } else if (tid < 192) {
        int e = tid - 128, q = e >> 3, j = e & 7;
        Cst[e] = 2.0f * cospif((float)((2 * j + 1) * q) / 16.0f);
    }
    __syncthreads();

    // ---- stage 1: f -> t.  map: o_local = tid>>4, pq0 = (tid&15)*4 ----
    {
        const int ol = tid >> 4;
        const int pq0 = (tid & 15) * 4;
        const float4* wp = (const float4*)(W +
            ((size_t)(s * 64 + oq * 16 + ol) << 11) + pq0);
        u64 a00 = 0, a01 = 0, a10 = 0, a11 = 0;
#pragma unroll
        for (int f = 0; f < 32; ++f) {
            float4 av = wp[f * 16];
            u64 p01 = pk2(av.x, av.y), p23 = pk2(av.z, av.w);
            float c0 = Ct2[0][f], c1 = Ct2[1][f];
            u64 cc0 = pk2(c0, c0), cc1 = pk2(c1, c1);
            fma2(a00, p01, cc0); fma2(a01, p23, cc0);
            fma2(a10, p01, cc1); fma2(a11, p23, cc1);
        }
        float2 v0 = up2(a00), v1 = up2(a01), v2 = up2(a10), v3 = up2(a11);
        *(float4*)&Y1[0][ol][pq0] = make_float4(v0.x, v0.y, v1.x, v1.y);
        *(float4*)&Y1[1][ol][pq0] = make_float4(v2.x, v2.y, v3.x, v3.y);
    }
    __syncthreads();

    // ---- stage 2: p -> i.  map: o = tid&15, i = (tid>>4)&7, qh = tid>>7 ----
    const int o2 = tid & 15;
    const int i2 = (tid >> 4) & 7;
    const int h2 = tid >> 7;
    {
        const int q0 = h2 * 4;
        u64 a00 = 0, a01 = 0, a10 = 0, a11 = 0;
#pragma unroll
        for (int p = 0; p < 8; ++p) {
            float c = Cs[i2 * 8 + p];
            u64 cc = pk2(c, c);
            float4 b0 = *(const float4*)&Y1[0][o2][p * 8 + q0];
            float4 b1 = *(const float4*)&Y1[1][o2][p * 8 + q0];
            fma2(a00, pk2(b0.x, b0.y), cc); fma2(a01, pk2(b0.z, b0.w), cc);
            fma2(a10, pk2(b1.x, b1.y), cc); fma2(a11, pk2(b1.z, b1.w), cc);
        }
        float2 v0 = up2(a00), v1 = up2(a01), v2 = up2(a10), v3 = up2(a11);
        *(float4*)&Y2[0][o2][i2 * 8 + q0] = make_float4(v0.x, v0.y, v1.x, v1.y);
        *(float4*)&Y2[1][o2][i2 * 8 + q0] = make_float4(v2.x, v2.y, v3.x, v3.y);
    }
    __syncthreads();

    // ---- stage 3: q -> j, scale 1/8, coalesced scatter (o fastest) ----
    {
        const int j0 = h2 * 4;
        float4 t0a = *(const float4*)&Y2[0][o2][i2 * 8];
        float4 t0b = *(const float4*)&Y2[0][o2][i2 * 8 + 4];
        float4 t1a = *(const float4*)&Y2[1][o2][i2 * 8];
        float4 t1b = *(const float4*)&Y2[1][o2][i2 * 8 + 4];
        float b0q[8] = {t0a.x, t0a.y, t0a.z, t0a.w, t0b.x, t0b.y, t0b.z, t0b.w};
        float b1q[8] = {t1a.x, t1a.y, t1a.z, t1a.w, t1b.x, t1b.y, t1b.z, t1b.w};
        u64 ac[4] = {};  // ac[j] packs (t0, t1)
#pragma unroll
        for (int q = 0; q < 8; ++q) {
            float4 cj = *(const float4*)&Cst[q * 8 + j0];
            u64 bp = pk2(b0q[q], b1q[q]);
            fma2(ac[0], bp, pk2(cj.x, cj.x));
            fma2(ac[1], bp, pk2(cj.y, cj.y));
            fma2(ac[2], bp, pk2(cj.z, cj.z));
            fma2(ac[3], bp, pk2(cj.w, cj.w));
        }
        // g_veff[s][t][i*8+j][o]; lanes vary o2 fastest -> coalesced 64B runs
        float* b0 = g_veff + (((size_t)(s * 32 + 2 * tp) << 6) + i2 * 8 + j0) * 64
                          + oq * 16 + o2;
        float* b1 = b0 + 4096;  // t+1
#pragma unroll
        for (int j = 0; j < 4; ++j) {
            float2 v = up2(ac[j]);
            b0[j * 64] = 0.125f * v.x;
            b1[j * 64] = 0.125f * v.y;
        }
    }
}

// ---------------------------------------------------------------------------
// main: 512 CTAs x 256 thr, occ 4. R4-EXACT GEMM core + fused epilogue.
// ---------------------------------------------------------------------------
__global__ void __launch_bounds__(256, 4) main_kernel(
    const float* __restrict__ x, const float* __restrict__ bias,
    float* __restrict__ out) {
    __shared__ __align__(16) float xs[2][32][68];  // [buf][ij][b]
    __shared__ __align__(16) float ws[2][32][64];  // [buf][ij][o]
    __shared__ int s_win;

    const int tid = threadIdx.x;
    const int bx = blockIdx.x;
    const int ks = bx & 15;
    const int mt = (bx >> 4) & 15;
    const int s = bx >> 8;

    const int ijp = tid & 15, bb = tid >> 4;  // load map (coalesced 128B rows)
    const int tx = tid & 15, ty = tid >> 4;   // compute map

    const float* xb = x + (size_t)(mt * 64 + bb * 4) * 32768 + (size_t)s * 16384 + 2 * ijp;

    u64 acc[2][4] = {};
    u64 xr[8];
    float4 wr0, wr1;

#define PH_T(ph) (ks * 2 + ((ph) >> 1))
#define PH_OFF(ph) ((size_t)(PH_T(ph)) * 64 + ((ph) & 1) * 32)

#define LDG_U(ph, u)                                                          \
    do {                                                                      \
        const u64* p = (const u64*)(xb + (size_t)(u) * 32768 + PH_OFF(ph));   \
        _Pragma("unroll") for (int c = 0; c < 8; ++c) xr[c] = p[c * 1024];    \
    } while (0)

#define STS_U(buf, u)                                                         \
    do {                                                                      \
        u64 s0 = add2(add2(xr[0], xr[1]), add2(xr[2], xr[3]));                \
        u64 s1 = add2(add2(xr[4], xr[5]), add2(xr[6], xr[7]));                \
        float2 v = up2(add2(s0, s1));                                         \
        xs[buf][2 * ijp][bb * 4 + (u)] = v.x;                                 \
        xs[buf][2 * ijp + 1][bb * 4 + (u)] = v.y;                             \
    } while (0)

#define LDG_W(ph)                                                             \
    do {                                                                      \
        const float4* wp = (const float4*)(g_veff +                          \
            (((size_t)s * 32 + PH_T(ph)) * 64 + ((ph) & 1) * 32) * 64);       \
        wr0 = wp[tid]; wr1 = wp[tid + 256];                                   \
    } while (0)

#define STS_W(buf)                                                            \
    do {                                                                      \
        float4* wd = (float4*)&ws[buf][0][0];                                 \
        wd[tid] = wr0; wd[tid + 256] = wr1;                                   \
    } while (0)

#define COMP8(buf, k0)                                                        \
    do {                                                                      \
        _Pragma("unroll") for (int k = (k0); k < (k0) + 8; ++k) {             \
            ulonglong2 xp = *(const ulonglong2*)&xs[buf][k][4 * ty];          \
            float4 wv = *(const float4*)&ws[buf][k][4 * tx];                  \
            u64 w0 = pk2(wv.x, wv.x), w1 = pk2(wv.y, wv.y);                   \
            u64 w2 = pk2(wv.z, wv.z), w3 = pk2(wv.w, wv.w);                   \
            fma2(acc[0][0], xp.x, w0); fma2(acc[1][0], xp.y, w0);             \
            fma2(acc[0][1], xp.x, w1); fma2(acc[1][1], xp.y, w1);             \
            fma2(acc[0][2], xp.x, w2); fma2(acc[1][2], xp.y, w2);             \
            fma2(acc[0][3], xp.x, w3); fma2(acc[1][3], xp.y, w3);             \
        }                                                                     \
    } while (0)

    // prologue: fill buffer 0 with phase 0
    LDG_W(0);
    LDG_U(0, 0); STS_U(0, 0);
    LDG_U(0, 1); STS_U(0, 1);
    LDG_U(0, 2); STS_U(0, 2);
    LDG_U(0, 3); STS_U(0, 3);
    STS_W(0);
    __syncthreads();

#pragma unroll
    for (int ph = 0; ph < 4; ++ph) {
        const int buf = ph & 1, nb = buf ^ 1;
        if (ph < 3) {
            LDG_W(ph + 1);
            LDG_U(ph + 1, 0); COMP8(buf, 0);  STS_U(nb, 0);
            LDG_U(ph + 1, 1); COMP8(buf, 8);  STS_U(nb, 1);
            LDG_U(ph + 1, 2); COMP8(buf, 16); STS_U(nb, 2);
            LDG_U(ph + 1, 3); COMP8(buf, 24); STS_U(nb, 3);
            STS_W(nb);
        } else {
            COMP8(buf, 0); COMP8(buf, 8); COMP8(buf, 16); COMP8(buf, 24);
        }
        __syncthreads();
    }

    // write partials: g_part[ks][b][s*64+o]
    {
        const int b0 = mt * 64 + 4 * ty;
        const int obase = s * 64 + 4 * tx;
#pragma unroll
        for (int p = 0; p < 2; ++p) {
            float2 c0 = up2(acc[p][0]), c1 = up2(acc[p][1]);
            float2 c2 = up2(acc[p][2]), c3 = up2(acc[p][3]);
            float4 r0 = make_float4(c0.x, c1.x, c2.x, c3.x);
            float4 r1 = make_float4(c0.y, c1.y, c2.y, c3.y);
            *(float4*)(g_part + ((size_t)ks << 17) + (size_t)(b0 + 2 * p) * 128 + obase) = r0;
            *(float4*)(g_part + ((size_t)ks << 17) + (size_t)(b0 + 2 * p + 1) * 128 + obase) = r1;
        }
    }

    // fused epilogue: last CTA of each (s,mt) group reduces its 64b x 64o block
    __threadfence();
    __syncthreads();
    if (tid == 0) {
        int old = atomicAdd(&g_grp[bx >> 4], 1);
        s_win = (old == 15);
        if (old == 15) g_grp[bx >> 4] = 0;  // self-reset for next replay
    }
    __syncthreads();

    if (s_win) {
        __threadfence();
#pragma unroll
        for (int u = 0; u < 4; ++u) {
            int v = tid + 256 * u;
            int bl = v >> 4, so4 = v & 15;
            size_t off = (size_t)(mt * 64 + bl) * 128 + s * 64 + so4 * 4;
            float4 bv = *(const float4*)(bias + s * 64 + so4 * 4);
            u64 a0 = pk2(bv.x, bv.y), a1 = pk2(bv.z, bv.w);
#pragma unroll
            for (int k = 0; k < KSPLIT; ++k) {
                ulonglong2 pp = *(const ulonglong2*)(g_part + ((size_t)k << 17) + off);
                a0 = add2(a0, pp.x);
                a1 = add2(a1, pp.y);
            }
            float2 f0 = up2(a0), f1 = up2(a1);
            float4 r;
            r.x = (f0.x >= 0.0f) ? f0.x : 0.02f * f0.x;
            r.y = (f0.y >= 0.0f) ? f0.y : 0.02f * f0.y;
            r.z = (f1.x >= 0.0f) ? f1.x : 0.02f * f1.x;
            r.w = (f1.y >= 0.0f) ? f1.y : 0.02f * f1.y;
            *(float4*)(out + off) = r;
        }
        if (tid == 0) {
            int d = atomicAdd(&g_done, 1);
            if (d == 31) g_done = 0;  // self-reset
        }
    }
}

// ---------------------------------------------------------------------------
extern "C" void kernel_launch(void* const* d_in, const int* in_sizes, int n_in,
                              void* d_out, int out_size) {
    const float* x = nullptr;
    const float* W = nullptr;
    const float* bias = nullptr;
    for (int i = 0; i < n_in; ++i) {
        if (in_sizes[i] == 1024 * 512 * 64) x = (const float*)d_in[i];
        else if (in_sizes[i] == NSW * NF * 32 * 64) W = (const float*)d_in[i];
        else if (in_sizes[i] == NSW * NF) bias = (const float*)d_in[i];
    }
    if (!x) x = (const float*)d_in[0];
    if (!W) W = (const float*)d_in[1];
    if (!bias) bias = (const float*)d_in[2];

    prep_kernel<<<128, 256>>>(W);
    main_kernel<<<NSW * MTILES * KSPLIT, 256>>>(x, bias, (float*)d_out);
}

// round 11
// speedup vs baseline: 1.2070x; 1.2070x over previous
#include <cuda_runtime.h>
#include <cstddef>
#include <cstdint>

// DCTFeatureModel — collapsed linear model:
// feat[b,s,o] = sum_{t,ij} xc[b,s,t,ij] * Veff[s,o,t,ij] + bias[s,o]
//   xc[b,s,t,ij]    = sum_c x[b, s*256 + c*32 + t, ij]
//   Veff[s,o,t,i,j] = (1/8) sum_{f,p,q} Ct[f,t] Cs[p,i] Cs[q,j] W[s,o,f,p,q]
// out[b, s*64+o] = leaky_relu(feat)
//
// R4-exact kernels; only change: streaming cache hints (.cs) on the x loads
// and g_part stores/loads so the once-touched x stream stops evicting the
// re-used g_veff (16 MB of re-reads) and g_part (8 MB) from L2.

#define NSW 2
#define NF 64
#define KSPLIT 16
#define MTILES 16

__device__ __align__(16) float g_veff[NSW * 32 * 64 * 64];        // [s][t][ij][o], 1 MB
__device__ __align__(16) float g_part[KSPLIT * 1024 * NSW * NF];  // 8 MB

typedef unsigned long long u64;

__device__ __forceinline__ u64 pk2(float a, float b) {
    u64 r; asm("mov.b64 %0,{%1,%2};" : "=l"(r) : "f"(a), "f"(b)); return r;
}
__device__ __forceinline__ float2 up2(u64 a) {
    float2 v; asm("mov.b64 {%0,%1},%2;" : "=f"(v.x), "=f"(v.y) : "l"(a)); return v;
}
__device__ __forceinline__ void fma2(u64& d, u64 a, u64 b) {
    asm("fma.rn.f32x2 %0,%1,%2,%0;" : "+l"(d) : "l"(a), "l"(b));
}
__device__ __forceinline__ u64 add2(u64 a, u64 b) {
    u64 r; asm("add.rn.f32x2 %0,%1,%2;" : "=l"(r) : "l"(a), "l"(b)); return r;
}

// ---------------------------------------------------------------------------
// prep: R4-exact. one CTA per (s,o), 128 CTAs, register-blocked stages.
// ---------------------------------------------------------------------------
__global__ void __launch_bounds__(256) prep_kernel(const float* __restrict__ W) {
    __shared__ __align__(16) float A[2048];
    __shared__ __align__(16) float Bf[2048];
    __shared__ __align__(16) float B2[2048];
    __shared__ __align__(16) float Ct[1024];
    __shared__ __align__(16) float Cs[64];
    __shared__ __align__(16) float Cst[64];

    const int tid = threadIdx.x;
    const int s = blockIdx.x >> 6;
    const int o = blockIdx.x & 63;

#pragma unroll
    for (int r = 0; r < 4; ++r) {
        int idx = tid + 256 * r;
        int t = idx >> 5, f = idx & 31;
        Ct[idx] = 2.0f * cospif((float)((2 * t + 1) * f) / 64.0f);
    }
    if (tid < 64) {
        int i = tid >> 3, p = tid & 7;
        Cs[tid] = 2.0f * cospif((float)((2 * i + 1) * p) / 16.0f);
    } else if (tid < 128) {
        int idx = tid - 64;
        int q = idx >> 3, j = idx & 7;
        Cst[idx] = 2.0f * cospif((float)((2 * j + 1) * q) / 16.0f);
    }
    {
        const float4* Wso = (const float4*)(W + ((size_t)(s * 64 + o) << 11));
        ((float4*)A)[tid] = Wso[tid];
        ((float4*)A)[tid + 256] = Wso[tid + 256];
    }
    __syncthreads();

    const int a = tid >> 4;
    const int t0 = 2 * a, t1 = 2 * a + 1;
    const int g16 = tid & 15;

    // stage 1: f -> t, tile 2t x 4pq
    {
        u64 ac00 = 0, ac01 = 0, ac10 = 0, ac11 = 0;
#pragma unroll
        for (int f = 0; f < 32; ++f) {
            float4 av = ((const float4*)A)[f * 16 + g16];
            u64 a01 = pk2(av.x, av.y), a23 = pk2(av.z, av.w);
            u64 w0 = pk2(Ct[t0 * 32 + f], Ct[t0 * 32 + f]);
            u64 w1 = pk2(Ct[t1 * 32 + f], Ct[t1 * 32 + f]);
            fma2(ac00, a01, w0); fma2(ac01, a23, w0);
            fma2(ac10, a01, w1); fma2(ac11, a23, w1);
        }
        float2 v0 = up2(ac00), v1 = up2(ac01), v2 = up2(ac10), v3 = up2(ac11);
        *(float4*)&Bf[t0 * 64 + 4 * g16] = make_float4(v0.x, v0.y, v1.x, v1.y);
        *(float4*)&Bf[t1 * 64 + 4 * g16] = make_float4(v2.x, v2.y, v3.x, v3.y);
    }
    __syncthreads();

    // stage 2: p -> i, tile 2t x i x 4q
    const int i8 = (tid >> 1) & 7;
    const int qg = tid & 1;
    {
        u64 ac00 = 0, ac01 = 0, ac10 = 0, ac11 = 0;
#pragma unroll
        for (int p = 0; p < 8; ++p) {
            float cs = Cs[i8 * 8 + p];
            u64 w = pk2(cs, cs);
            float4 b0 = *(const float4*)&Bf[t0 * 64 + p * 8 + 4 * qg];
            float4 b1 = *(const float4*)&Bf[t1 * 64 + p * 8 + 4 * qg];
            fma2(ac00, pk2(b0.x, b0.y), w); fma2(ac01, pk2(b0.z, b0.w), w);
            fma2(ac10, pk2(b1.x, b1.y), w); fma2(ac11, pk2(b1.z, b1.w), w);
        }
        float2 v0 = up2(ac00), v1 = up2(ac01), v2 = up2(ac10), v3 = up2(ac11);
        *(float4*)&B2[t0 * 64 + i8 * 8 + 4 * qg] = make_float4(v0.x, v0.y, v1.x, v1.y);
        *(float4*)&B2[t1 * 64 + i8 * 8 + 4 * qg] = make_float4(v2.x, v2.y, v3.x, v3.y);
    }
    __syncthreads();

    // stage 3: q -> j, scale 1/8, scatter
    {
        const int jg = qg;
        float4 r0a = *(const float4*)&B2[t0 * 64 + i8 * 8];
        float4 r0b = *(const float4*)&B2[t0 * 64 + i8 * 8 + 4];
        float4 r1a = *(const float4*)&B2[t1 * 64 + i8 * 8];
        float4 r1b = *(const float4*)&B2[t1 * 64 + i8 * 8 + 4];
        float b0q[8] = {r0a.x, r0a.y, r0a.z, r0a.w, r0b.x, r0b.y, r0b.z, r0b.w};
        float b1q[8] = {r1a.x, r1a.y, r1a.z, r1a.w, r1b.x, r1b.y, r1b.z, r1b.w};
        u64 ac[4] = {};
#pragma unroll
        for (int q = 0; q < 8; ++q) {
            float4 cj = *(const float4*)&Cst[q * 8 + 4 * jg];
            u64 bp = pk2(b0q[q], b1q[q]);
            fma2(ac[0], bp, pk2(cj.x, cj.x));
            fma2(ac[1], bp, pk2(cj.y, cj.y));
            fma2(ac[2], bp, pk2(cj.z, cj.z));
            fma2(ac[3], bp, pk2(cj.w, cj.w));
        }
        float* base0 = g_veff + (((size_t)(s * 32 + t0) << 6) + i8 * 8 + 4 * jg) * 64 + o;
        float* base1 = g_veff + (((size_t)(s * 32 + t1) << 6) + i8 * 8 + 4 * jg) * 64 + o;
#pragma unroll
        for (int j = 0; j < 4; ++j) {
            float2 v = up2(ac[j]);
            base0[j * 64] = 0.125f * v.x;
            base1[j * 64] = 0.125f * v.y;
        }
    }
}

// ---------------------------------------------------------------------------
// main: 512 CTAs x 256 thr, occ 4. R4-exact schedule; x loads use .cs
// (evict-first) so the 134MB once-touched stream stops thrashing L2.
// ---------------------------------------------------------------------------
__global__ void __launch_bounds__(256, 4) main_kernel(const float* __restrict__ x) {
    __shared__ __align__(16) float xs[2][32][68];  // [buf][ij][b]
    __shared__ __align__(16) float ws[2][32][64];  // [buf][ij][o]

    const int tid = threadIdx.x;
    const int bx = blockIdx.x;
    const int ks = bx & 15;
    const int mt = (bx >> 4) & 15;
    const int s = bx >> 8;

    const int ijp = tid & 15, bb = tid >> 4;  // load map (coalesced 128B rows)
    const int tx = tid & 15, ty = tid >> 4;   // compute map

    const float* xb = x + (size_t)(mt * 64 + bb * 4) * 32768 + (size_t)s * 16384 + 2 * ijp;

    u64 acc[2][4] = {};
    u64 xr[8];
    float4 wr0, wr1;

#define PH_T(ph) (ks * 2 + ((ph) >> 1))
#define PH_OFF(ph) ((size_t)(PH_T(ph)) * 64 + ((ph) & 1) * 32)

#define LDG_U(ph, u)                                                          \
    do {                                                                      \
        const u64* p = (const u64*)(xb + (size_t)(u) * 32768 + PH_OFF(ph));   \
        _Pragma("unroll") for (int c = 0; c < 8; ++c) xr[c] = __ldcs(p + c * 1024); \
    } while (0)

#define STS_U(buf, u)                                                         \
    do {                                                                      \
        u64 s0 = add2(add2(xr[0], xr[1]), add2(xr[2], xr[3]));                \
        u64 s1 = add2(add2(xr[4], xr[5]), add2(xr[6], xr[7]));                \
        float2 v = up2(add2(s0, s1));                                         \
        xs[buf][2 * ijp][bb * 4 + (u)] = v.x;                                 \
        xs[buf][2 * ijp + 1][bb * 4 + (u)] = v.y;                             \
    } while (0)

#define LDG_W(ph)                                                             \
    do {                                                                      \
        const float4* wp = (const float4*)(g_veff +                          \
            (((size_t)s * 32 + PH_T(ph)) * 64 + ((ph) & 1) * 32) * 64);       \
        wr0 = wp[tid]; wr1 = wp[tid + 256];                                   \
    } while (0)

#define STS_W(buf)                                                            \
    do {                                                                      \
        float4* wd = (float4*)&ws[buf][0][0];                                 \
        wd[tid] = wr0; wd[tid + 256] = wr1;                                   \
    } while (0)

#define COMP8(buf, k0)                                                        \
    do {                                                                      \
        _Pragma("unroll") for (int k = (k0); k < (k0) + 8; ++k) {             \
            ulonglong2 xp = *(const ulonglong2*)&xs[buf][k][4 * ty];          \
            float4 wv = *(const float4*)&ws[buf][k][4 * tx];                  \
            u64 w0 = pk2(wv.x, wv.x), w1 = pk2(wv.y, wv.y);                   \
            u64 w2 = pk2(wv.z, wv.z), w3 = pk2(wv.w, wv.w);                   \
            fma2(acc[0][0], xp.x, w0); fma2(acc[1][0], xp.y, w0);             \
            fma2(acc[0][1], xp.x, w1); fma2(acc[1][1], xp.y, w1);             \
            fma2(acc[0][2], xp.x, w2); fma2(acc[1][2], xp.y, w2);             \
            fma2(acc[0][3], xp.x, w3); fma2(acc[1][3], xp.y, w3);             \
        }                                                                     \
    } while (0)

    // prologue: fill buffer 0 with phase 0
    LDG_W(0);
    LDG_U(0, 0); STS_U(0, 0);
    LDG_U(0, 1); STS_U(0, 1);
    LDG_U(0, 2); STS_U(0, 2);
    LDG_U(0, 3); STS_U(0, 3);
    STS_W(0);
    __syncthreads();

#pragma unroll
    for (int ph = 0; ph < 4; ++ph) {
        const int buf = ph & 1, nb = buf ^ 1;
        if (ph < 3) {
            LDG_W(ph + 1);
            LDG_U(ph + 1, 0); COMP8(buf, 0);  STS_U(nb, 0);
            LDG_U(ph + 1, 1); COMP8(buf, 8);  STS_U(nb, 1);
            LDG_U(ph + 1, 2); COMP8(buf, 16); STS_U(nb, 2);
            LDG_U(ph + 1, 3); COMP8(buf, 24); STS_U(nb, 3);
            STS_W(nb);
        } else {
            COMP8(buf, 0); COMP8(buf, 8); COMP8(buf, 16); COMP8(buf, 24);
        }
        __syncthreads();
    }

    // write partials: g_part[ks][b][s*64+o] (streaming: written once, read once)
    const int b0 = mt * 64 + 4 * ty;
    const int obase = s * 64 + 4 * tx;
#pragma unroll
    for (int p = 0; p < 2; ++p) {
        float2 c0 = up2(acc[p][0]), c1 = up2(acc[p][1]);
        float2 c2 = up2(acc[p][2]), c3 = up2(acc[p][3]);
        float4 r0 = make_float4(c0.x, c1.x, c2.x, c3.x);
        float4 r1 = make_float4(c0.y, c1.y, c2.y, c3.y);
        __stcs((float4*)(g_part + ((size_t)ks << 17) + (size_t)(b0 + 2 * p) * 128 + obase), r0);
        __stcs((float4*)(g_part + ((size_t)ks << 17) + (size_t)(b0 + 2 * p + 1) * 128 + obase), r1);
    }
}

// ---------------------------------------------------------------------------
// epilogue: sum KSPLIT partials + bias, LeakyReLU (R4 structure; .cs reads)
// ---------------------------------------------------------------------------
__global__ void __launch_bounds__(256) epi_kernel(const float* __restrict__ bias,
                                                  float* __restrict__ out) {
    const int i4 = (blockIdx.x * 256 + threadIdx.x) * 4;
    float4 bv = *(const float4*)(bias + (i4 & 127));
    u64 a0 = pk2(bv.x, bv.y), a1 = pk2(bv.z, bv.w);
#pragma unroll
    for (int k = 0; k < KSPLIT; ++k) {
        const ulonglong2* pp = (const ulonglong2*)(g_part + ((size_t)k << 17) + i4);
        ulonglong2 p;
        p.x = __ldcs(&pp->x);
        p.y = __ldcs(&pp->y);
        a0 = add2(a0, p.x);
        a1 = add2(a1, p.y);
    }
    float2 f0 = up2(a0), f1 = up2(a1);
    float4 r;
    r.x = (f0.x >= 0.0f) ? f0.x : 0.02f * f0.x;
    r.y = (f0.y >= 0.0f) ? f0.y : 0.02f * f0.y;
    r.z = (f1.x >= 0.0f) ? f1.x : 0.02f * f1.x;
    r.w = (f1.y >= 0.0f) ? f1.y : 0.02f * f1.y;
    *(float4*)(out + i4) = r;
}

// ---------------------------------------------------------------------------
extern "C" void kernel_launch(void* const* d_in, const int* in_sizes, int n_in,
                              void* d_out, int out_size) {
    const float* x = nullptr;
    const float* W = nullptr;
    const float* bias = nullptr;
    for (int i = 0; i < n_in; ++i) {
        if (in_sizes[i] == 1024 * 512 * 64) x = (const float*)d_in[i];
        else if (in_sizes[i] == NSW * NF * 32 * 64) W = (const float*)d_in[i];
        else if (in_sizes[i] == NSW * NF) bias = (const float*)d_in[i];
    }
    if (!x) x = (const float*)d_in[0];
    if (!W) W = (const float*)d_in[1];
    if (!bias) bias = (const float*)d_in[2];

    prep_kernel<<<NSW * NF, 256>>>(W);
    main_kernel<<<NSW * MTILES * KSPLIT, 256>>>(x);
    epi_kernel<<<(1024 * NSW * NF) / (256 * 4), 256>>>(bias, (float*)d_out);
}